// round 12
// baseline (speedup 1.0000x reference)
#include <cuda_runtime.h>

// x: (8, 64, 128, 128) fp32  ->  out: (8, 64, 384, 384) fp32
//
// FINAL converged kernel (best measured 51.2us; HBM write-stream bound).
//
// Math: with RATIO=0.5, KS=3 the reference collapses to a separable 3x
// half-pixel resample. Row dedup: out[3i] == out[3(i-1)+2], so the distinct
// output rows are:
//   center(i) = Hresample(x[i])              -> row 3i+1
//   avg(i)    = Hresample(0.5*(x[i]+x[i+1])) -> rows 3i+2 and 3i+3
//   row 0 = avg(0), row 383 = avg(126)   (reflect padding at borders)
// Hresample: out col 3j+kj: kj=0 -> h[j-1], kj=1 -> c[j], kj=2 -> h[j];
// h[j] = 0.5*(c[j]+c[refl(j+1)]); reflect: -1 -> 1, 128 -> 126.
//
// Design: warp per input row i.
//  - 2x LDG.128 (default policy: row i+1 L1-hits for the adjacent warp)
//  - vertical blend in regs, 2x STS.128 into bank-conflict-free padded smem
//  - gather indices (q, r, reflect) computed ONCE per output float4 and
//    reused for both the center and avg rows (avg gathered once, stored to
//    both duplicate destination rows)
//  - all output stores: coalesced, full-sector STG.128 .cs (streaming,
//    evict-first; 302MB output is write-once)
//
// Validated ceiling: LSU STG.128, TMA bulk store, and STG.256 all pin DRAM
// at 68-70% -> L2/HBM write-turnaround limit for a 9:1 write:read stream,
// not an SM-side resource. 1.22x above the 42us pure-bandwidth floor.

#define H 128
#define W 128
#define W4 (W / 4)
#define OW 384
#define OW4 (OW / 4)
#define NW 8
#define CPAD 144              // 128 + 4 pad per 32 floats (keeps 16B align)

__device__ __forceinline__ int swz(int j) { return j + ((j >> 5) << 2); }

__device__ __forceinline__ float4 gatherv(const float* __restrict__ C,
                                          int aq, int aq1, int at, int r)
{
    const float cq  = C[aq];
    const float cq1 = C[aq1];
    const float ct  = C[at];

    const float h0 = 0.5f * (cq + cq1);
    const float ex = 0.5f * (ct + ((r == 0) ? cq : cq1));

    float4 v;
    v.x = (r == 0) ? ex  : ((r == 1) ? cq  : h0);
    v.y = (r == 0) ? cq  : h0;
    v.z = (r == 2) ? cq1 : h0;
    v.w = (r == 2) ? ex  : ((r == 1) ? cq1 : h0);
    return v;
}

__global__ __launch_bounds__(NW * 32) void rf_scale_kernel(
    const float4* __restrict__ x, float4* __restrict__ out)
{
    __shared__ float Cs[NW][2][CPAD];   // [0] = center row, [1] = avg row

    const int lane = threadIdx.x & 31;
    const int w    = threadIdx.x >> 5;

    const int i  = blockIdx.x * NW + w;          // input row 0..127
    const int bc = blockIdx.y;

    const float4* __restrict__ xin = x + (size_t)bc * (H * W4);

    // i<127: avg(i) with row i+1; i==127: compute avg(126) for row 383.
    const int i1 = (i < H - 1) ? i + 1 : i - 1;
    const float4 b = xin[i  * W4 + lane];
    const float4 d = xin[i1 * W4 + lane];

    float4 av;
    av.x = 0.5f * (b.x + d.x);
    av.y = 0.5f * (b.y + d.y);
    av.z = 0.5f * (b.z + d.z);
    av.w = 0.5f * (b.w + d.w);

    const int so = swz(lane << 2);
    *reinterpret_cast<float4*>(&Cs[w][0][so]) = b;
    *reinterpret_cast<float4*>(&Cs[w][1][so]) = av;
    __syncwarp();

    const float* __restrict__ Cc = Cs[w][0];
    const float* __restrict__ Ca = Cs[w][1];

    float4* __restrict__ obase =
        out + (size_t)bc * (OW * OW4) + (size_t)(3 * i) * OW4;

    const bool last = (i == H - 1);

    #pragma unroll
    for (int s = 0; s < 3; s++) {
        const int g  = lane + (s << 5);                       // 0..95
        const int fg = g << 2;
        const int q  = (int)(((unsigned)fg * 21846u) >> 16);  // fg/3 (exact)
        const int r  = fg - 3 * q;

        const int qt = (r == 0) ? ((q == 0) ? 1 : q - 1)
                                : ((q == W - 2) ? (W - 2) : q + 2);

        const int aq  = swz(q);
        const int aq1 = swz(q + 1);
        const int at  = swz(qt);

        // center(i) -> row 3i+1
        __stcs(&obase[OW4 + g], gatherv(Cc, aq, aq1, at, r));

        const float4 v = gatherv(Ca, aq, aq1, at, r);
        if (!last) {
            __stcs(&obase[2 * OW4 + g], v);           // row 3i+2 = avg(i)
            __stcs(&obase[3 * OW4 + g], v);           // row 3i+3 = avg(i)
            if (i == 0) __stcs(&obase[g], v);         // row 0    = avg(0)
        } else {
            __stcs(&obase[2 * OW4 + g], v);           // row 383  = avg(126)
        }
    }
}

extern "C" void kernel_launch(void* const* d_in, const int* in_sizes, int n_in,
                              void* d_out, int out_size)
{
    const float4* x = (const float4*)d_in[0];
    float4* out = (float4*)d_out;

    const int n_bc = in_sizes[0] / (H * W);   // 512

    dim3 grid(H / NW, n_bc);                  // (16, 512)
    dim3 block(NW * 32);                      // 256
    rf_scale_kernel<<<grid, block>>>(x, out);
}

// round 13
// speedup vs baseline: 1.2478x; 1.2478x over previous
#include <cuda_runtime.h>

// x: (8, 64, 128, 128) fp32  ->  out: (8, 64, 384, 384) fp32
//
// Math: with RATIO=0.5, KS=3 the reference collapses to a separable 3x
// half-pixel resample. Row dedup: out[3i] == out[3(i-1)+2]; distinct rows:
//   center(i) = Hresample(x[i])              -> row 3i+1
//   avg(i)    = Hresample(0.5*(x[i]+x[i+1])) -> rows 3i+2 and 3i+3
//   row 0 = avg(0), row 383 = avg(126)   (reflect padding)
// Hresample: out col 3j+kj: kj=0 -> h[j-1], kj=1 -> c[j], kj=2 -> h[j];
// h[j] = 0.5*(c[j]+c[refl(j+1)]); reflect: -1 -> 1, 128 -> 126.
//
// R13: center/avg rows stored INTERLEAVED in smem as float2, so each gather
// position is one LDS.64 serving both output rows (9 LDS/warp instead of 18,
// same wavefront bytes). Store side stays 2x STS.128 (interleaved pairs are
// contiguous and 16B-aligned). Everything else = converged R7 design:
// warp per input row, indices computed once per output float4, coalesced
// full-sector STG.128 .cs streaming stores.

#define H 128
#define W 128
#define W4 (W / 4)
#define OW 384
#define OW4 (OW / 4)
#define NW 8
#define CS2 160               // float2 slots per warp (max index 141, padded)

// pad 2 slots per 16: breaks q / q+16 bank collision at 8B stride
__device__ __forceinline__ int swz2(int q) { return q + ((q >> 4) << 1); }

__global__ __launch_bounds__(NW * 32) void rf_scale_kernel(
    const float4* __restrict__ x, float4* __restrict__ out)
{
    __shared__ float2 Cs[NW][CS2];   // Cs[w][m] = {center[q], avg[q]}

    const int lane = threadIdx.x & 31;
    const int w    = threadIdx.x >> 5;

    const int i  = blockIdx.x * NW + w;          // input row 0..127
    const int bc = blockIdx.y;

    const float4* __restrict__ xin = x + (size_t)bc * (H * W4);

    // i<127: avg(i) with row i+1; i==127: compute avg(126) for row 383.
    const int i1 = (i < H - 1) ? i + 1 : i - 1;
    const float4 b = xin[i  * W4 + lane];
    const float4 d = xin[i1 * W4 + lane];

    float4 av;
    av.x = 0.5f * (b.x + d.x);
    av.y = 0.5f * (b.y + d.y);
    av.z = 0.5f * (b.z + d.z);
    av.w = 0.5f * (b.w + d.w);

    // Interleaved store: {b.x,av.x,b.y,av.y} and {b.z,av.z,b.w,av.w}.
    // m0 = swz2(4*lane); 8*m0 is 16B-aligned and k=0..3 never crosses a
    // 16-block, so two STS.128 cover all four float2 slots.
    {
        const int m0 = swz2(lane << 2);
        float4* p = reinterpret_cast<float4*>(&Cs[w][m0]);
        p[0] = make_float4(b.x, av.x, b.y, av.y);
        p[1] = make_float4(b.z, av.z, b.w, av.w);
    }
    __syncwarp();

    const float2* __restrict__ C = Cs[w];

    float4* __restrict__ obase =
        out + (size_t)bc * (OW * OW4) + (size_t)(3 * i) * OW4;

    const bool last = (i == H - 1);

    #pragma unroll
    for (int s = 0; s < 3; s++) {
        const int g  = lane + (s << 5);                       // 0..95
        const int fg = g << 2;
        const int q  = (int)(((unsigned)fg * 21846u) >> 16);  // fg/3 (exact)
        const int r  = fg - 3 * q;

        const int qt = (r == 0) ? ((q == 0) ? 1 : q - 1)
                                : ((q == W - 2) ? (W - 2) : q + 2);

        const float2 cq  = C[swz2(q)];
        const float2 cq1 = C[swz2(q + 1)];
        const float2 ct  = C[swz2(qt)];

        // center (.x fields)
        const float h0c = 0.5f * (cq.x + cq1.x);
        const float exc = 0.5f * (ct.x + ((r == 0) ? cq.x : cq1.x));
        float4 vc;
        vc.x = (r == 0) ? exc  : ((r == 1) ? cq.x  : h0c);
        vc.y = (r == 0) ? cq.x : h0c;
        vc.z = (r == 2) ? cq1.x : h0c;
        vc.w = (r == 2) ? exc  : ((r == 1) ? cq1.x : h0c);

        // avg (.y fields)
        const float h0a = 0.5f * (cq.y + cq1.y);
        const float exa = 0.5f * (ct.y + ((r == 0) ? cq.y : cq1.y));
        float4 va;
        va.x = (r == 0) ? exa  : ((r == 1) ? cq.y  : h0a);
        va.y = (r == 0) ? cq.y : h0a;
        va.z = (r == 2) ? cq1.y : h0a;
        va.w = (r == 2) ? exa  : ((r == 1) ? cq1.y : h0a);

        // center(i) -> row 3i+1
        __stcs(&obase[OW4 + g], vc);

        if (!last) {
            __stcs(&obase[2 * OW4 + g], va);          // row 3i+2 = avg(i)
            __stcs(&obase[3 * OW4 + g], va);          // row 3i+3 = avg(i)
            if (i == 0) __stcs(&obase[g], va);        // row 0    = avg(0)
        } else {
            __stcs(&obase[2 * OW4 + g], va);          // row 383  = avg(126)
        }
    }
}

extern "C" void kernel_launch(void* const* d_in, const int* in_sizes, int n_in,
                              void* d_out, int out_size)
{
    const float4* x = (const float4*)d_in[0];
    float4* out = (float4*)d_out;

    const int n_bc = in_sizes[0] / (H * W);   // 512

    dim3 grid(H / NW, n_bc);                  // (16, 512)
    dim3 block(NW * 32);                      // 256
    rf_scale_kernel<<<grid, block>>>(x, out);
}

// round 14
// speedup vs baseline: 1.2636x; 1.0126x over previous
#include <cuda_runtime.h>

// x: (8, 64, 128, 128) fp32  ->  out: (8, 64, 384, 384) fp32
//
// FINAL kernel (best measured: 51.2us wall / 50.5us ncu; HBM write-bound).
//
// Math: with RATIO=0.5, KS=3 the reference collapses to a separable 3x
// half-pixel resample. Row dedup: out[3i] == out[3(i-1)+2]; distinct rows:
//   center(i) = Hresample(x[i])              -> row 3i+1
//   avg(i)    = Hresample(0.5*(x[i]+x[i+1])) -> rows 3i+2 and 3i+3
//   row 0 = avg(0), row 383 = avg(126)   (reflect padding)
// Hresample: out col 3j+kj: kj=0 -> h[j-1], kj=1 -> c[j], kj=2 -> h[j];
// h[j] = 0.5*(c[j]+c[refl(j+1)]); reflect: -1 -> 1, 128 -> 126.
//
// Design: warp per input row i.
//  - 2x LDG.128 (default policy: row i+1 L1-hits for the adjacent warp)
//  - vertical blend in regs; center/avg stored INTERLEAVED in smem as
//    float2 so each gather position is ONE LDS.64 serving both output rows
//    (9 LDS/warp instead of 18; robust if the L1TEX-bound machine regime
//    recurs), via 2x aligned STS.128
//  - gather indices (q, r, reflect) computed once per output float4,
//    reused for center and avg; avg gathered once, stored to both
//    duplicate destination rows
//  - all output stores: coalesced full-sector STG.128 .cs (streaming,
//    evict-first; 302MB output is write-once)
//
// Validated ceiling: LSU STG.128, TMA bulk store, and STG.256 all pin DRAM
// at 68-70% -> L2/HBM write-turnaround limit for a 9:1 write:read stream.
// 1.22x above the 42us pure-bandwidth floor; SM-side pipes all <70%.

#define H 128
#define W 128
#define W4 (W / 4)
#define OW 384
#define OW4 (OW / 4)
#define NW 8
#define CS2 160               // float2 slots per warp (max index 141, padded)

// pad 2 slots per 16: breaks q / q+16 bank collision at 8B stride
__device__ __forceinline__ int swz2(int q) { return q + ((q >> 4) << 1); }

__global__ __launch_bounds__(NW * 32) void rf_scale_kernel(
    const float4* __restrict__ x, float4* __restrict__ out)
{
    __shared__ float2 Cs[NW][CS2];   // Cs[w][m] = {center[q], avg[q]}

    const int lane = threadIdx.x & 31;
    const int w    = threadIdx.x >> 5;

    const int i  = blockIdx.x * NW + w;          // input row 0..127
    const int bc = blockIdx.y;

    const float4* __restrict__ xin = x + (size_t)bc * (H * W4);

    // i<127: avg(i) with row i+1; i==127: compute avg(126) for row 383.
    const int i1 = (i < H - 1) ? i + 1 : i - 1;
    const float4 b = xin[i  * W4 + lane];
    const float4 d = xin[i1 * W4 + lane];

    float4 av;
    av.x = 0.5f * (b.x + d.x);
    av.y = 0.5f * (b.y + d.y);
    av.z = 0.5f * (b.z + d.z);
    av.w = 0.5f * (b.w + d.w);

    // Interleaved store: {b.x,av.x,b.y,av.y} and {b.z,av.z,b.w,av.w}.
    // m0 = swz2(4*lane); 8*m0 is 16B-aligned and k=0..3 never crosses a
    // 16-slot block, so two STS.128 cover all four float2 slots.
    {
        const int m0 = swz2(lane << 2);
        float4* p = reinterpret_cast<float4*>(&Cs[w][m0]);
        p[0] = make_float4(b.x, av.x, b.y, av.y);
        p[1] = make_float4(b.z, av.z, b.w, av.w);
    }
    __syncwarp();

    const float2* __restrict__ C = Cs[w];

    float4* __restrict__ obase =
        out + (size_t)bc * (OW * OW4) + (size_t)(3 * i) * OW4;

    const bool last = (i == H - 1);

    #pragma unroll
    for (int s = 0; s < 3; s++) {
        const int g  = lane + (s << 5);                       // 0..95
        const int fg = g << 2;
        const int q  = (int)(((unsigned)fg * 21846u) >> 16);  // fg/3 (exact)
        const int r  = fg - 3 * q;

        const int qt = (r == 0) ? ((q == 0) ? 1 : q - 1)
                                : ((q == W - 2) ? (W - 2) : q + 2);

        const float2 cq  = C[swz2(q)];
        const float2 cq1 = C[swz2(q + 1)];
        const float2 ct  = C[swz2(qt)];

        // center (.x fields)
        const float h0c = 0.5f * (cq.x + cq1.x);
        const float exc = 0.5f * (ct.x + ((r == 0) ? cq.x : cq1.x));
        float4 vc;
        vc.x = (r == 0) ? exc  : ((r == 1) ? cq.x  : h0c);
        vc.y = (r == 0) ? cq.x : h0c;
        vc.z = (r == 2) ? cq1.x : h0c;
        vc.w = (r == 2) ? exc  : ((r == 1) ? cq1.x : h0c);

        // avg (.y fields)
        const float h0a = 0.5f * (cq.y + cq1.y);
        const float exa = 0.5f * (ct.y + ((r == 0) ? cq.y : cq1.y));
        float4 va;
        va.x = (r == 0) ? exa  : ((r == 1) ? cq.y  : h0a);
        va.y = (r == 0) ? cq.y : h0a;
        va.z = (r == 2) ? cq1.y : h0a;
        va.w = (r == 2) ? exa  : ((r == 1) ? cq1.y : h0a);

        // center(i) -> row 3i+1
        __stcs(&obase[OW4 + g], vc);

        if (!last) {
            __stcs(&obase[2 * OW4 + g], va);          // row 3i+2 = avg(i)
            __stcs(&obase[3 * OW4 + g], va);          // row 3i+3 = avg(i)
            if (i == 0) __stcs(&obase[g], va);        // row 0    = avg(0)
        } else {
            __stcs(&obase[2 * OW4 + g], va);          // row 383  = avg(126)
        }
    }
}

extern "C" void kernel_launch(void* const* d_in, const int* in_sizes, int n_in,
                              void* d_out, int out_size)
{
    const float4* x = (const float4*)d_in[0];
    float4* out = (float4*)d_out;

    const int n_bc = in_sizes[0] / (H * W);   // 512

    dim3 grid(H / NW, n_bc);                  // (16, 512)
    dim3 block(NW * 32);                      // 256
    rf_scale_kernel<<<grid, block>>>(x, out);
}